// round 2
// baseline (speedup 1.0000x reference)
#include <cuda_runtime.h>
#include <math.h>

#define C_IN 256
#define HH   30
#define WW   40
#define BB   4
#define TT   4
#define HW_  (HH*WW)          // 1200
#define CHW  (C_IN*HW_)       // 307200

// ---------------- scratch (device globals: no allocation allowed) ----------
__device__ float g_h  [BB*CHW];
__device__ float g_c  [BB*CHW];
__device__ float g_att[BB*CHW];
__device__ float g_e  [BB*HW_];
__device__ float g_a  [BB*HW_];
__device__ float g_xt [BB*CHW];
__device__ float g_g  [BB*4*CHW];

// ---------------- h0 = c0 = sum_t x ----------------------------------------
__global__ void init_hc_k(const float* __restrict__ x) {
    int i = blockIdx.x * blockDim.x + threadIdx.x;
    if (i >= BB*CHW) return;
    int b = i / CHW, r = i % CHW;
    float s = 0.f;
#pragma unroll
    for (int t = 0; t < TT; t++) s += x[((long)(b*TT + t))*CHW + r];
    g_h[i] = s;
    g_c[i] = s;
}

// ---------------- dual 3x3 conv: out = conv(in1,W1)+conv(in2,W2)+b1+b2 ------
// HWIO weights: W[ky][kx][ci][co].  Tile: 64 co x (2 rows x 40 cols).
template<int COUT, bool DO_TANH>
__global__ __launch_bounds__(256)
void conv_dual_k(const float* __restrict__ in1, long bs1,
                 const float* __restrict__ W1,
                 const float* __restrict__ in2, long bs2,
                 const float* __restrict__ W2,
                 const float* __restrict__ bias1,
                 const float* __restrict__ bias2,
                 float* __restrict__ out)
{
    __shared__ __align__(16) float sIn[2][8][4][44];   // [input][ci][row][x+1]
    __shared__ __align__(16) float sW [2][8][9][64];   // [input][ci][tap][co]

    const int tid  = threadIdx.x;
    const int row0 = blockIdx.x * 2;
    const int co0  = blockIdx.y * 64;
    const int b    = blockIdx.z;

    const float* base1 = in1 + (long)b * bs1;
    const float* base2 = in2 + (long)b * bs2;

    const int co_t = tid & 15;   // 16 co-groups of 4
    const int px_t = tid >> 4;   // 16 pixel-groups of 5

    int py[5], px[5];
#pragma unroll
    for (int k = 0; k < 5; k++) {
        int p = px_t * 5 + k;    // 0..79 over 2x40 tile
        py[k] = p / 40;
        px[k] = p % 40;
    }

    float acc[5][4];
#pragma unroll
    for (int k = 0; k < 5; k++)
#pragma unroll
        for (int c = 0; c < 4; c++) acc[k][c] = 0.f;

    for (int ci0 = 0; ci0 < C_IN; ci0 += 8) {
        __syncthreads();
        // stage input slabs: 2 inputs x 8 ci x 4 rows x 42 cols
        for (int idx = tid; idx < 2*8*4*42; idx += 256) {
            int xw  = idx % 42;
            int rem = idx / 42;
            int r   = rem & 3;  rem >>= 2;
            int ci  = rem & 7;
            int j   = rem >> 3;
            int y   = row0 - 1 + r;
            int xx  = xw - 1;
            float v = 0.f;
            if ((unsigned)y < (unsigned)HH && (unsigned)xx < (unsigned)WW) {
                const float* base = j ? base2 : base1;
                v = base[((long)(ci0 + ci) * HH + y) * WW + xx];
            }
            sIn[j][ci][r][xw] = v;
        }
        // stage weights: 2 x 8 x 9 x 64
        for (int idx = tid; idx < 2*8*9*64; idx += 256) {
            int co  = idx & 63;
            int rem = idx >> 6;
            int t   = rem % 9;  rem /= 9;
            int ci  = rem & 7;
            int j   = rem >> 3;
            const float* Wp = j ? W2 : W1;
            sW[j][ci][t][co] = Wp[((long)(t * C_IN + ci0 + ci)) * COUT + co0 + co];
        }
        __syncthreads();

#pragma unroll
        for (int ci = 0; ci < 8; ci++) {
#pragma unroll
            for (int t = 0; t < 9; t++) {
                const int ky = t / 3, kx = t % 3;
                float4 w1 = *(const float4*)&sW[0][ci][t][co_t * 4];
                float4 w2 = *(const float4*)&sW[1][ci][t][co_t * 4];
#pragma unroll
                for (int k = 0; k < 5; k++) {
                    float v1 = sIn[0][ci][py[k] + ky][px[k] + kx];
                    float v2 = sIn[1][ci][py[k] + ky][px[k] + kx];
                    acc[k][0] += v1 * w1.x + v2 * w2.x;
                    acc[k][1] += v1 * w1.y + v2 * w2.y;
                    acc[k][2] += v1 * w1.z + v2 * w2.z;
                    acc[k][3] += v1 * w1.w + v2 * w2.w;
                }
            }
        }
    }

#pragma unroll
    for (int c = 0; c < 4; c++) {
        int co = co0 + co_t * 4 + c;
        float bz = bias1[co] + bias2[co];
#pragma unroll
        for (int k = 0; k < 5; k++) {
            float v = acc[k][c] + bz;
            if (DO_TANH) v = tanhf(v);
            out[((long)(b * COUT + co) * HH + row0 + py[k]) * WW + px[k]] = v;
        }
    }
}

// ---------------- e = conv3x3(att, Va)  (CA=256 -> 1, no bias) --------------
__global__ void econv_k(const float* __restrict__ att,
                        const float* __restrict__ Va,
                        float* __restrict__ e)
{
    int i = blockIdx.x * blockDim.x + threadIdx.x;
    if (i >= BB*HW_) return;
    int b = i / HW_, p = i % HW_;
    int y = p / WW, x = p % WW;
    const float* ab = att + (long)b * CHW;
    float s0 = 0.f, s1 = 0.f;
    for (int ci = 0; ci < C_IN; ci += 2) {
        const float* apA = ab + (long)ci * HW_;
        const float* apB = apA + HW_;
#pragma unroll
        for (int ky = 0; ky < 3; ky++) {
            int yy = y + ky - 1;
            if ((unsigned)yy >= (unsigned)HH) continue;
#pragma unroll
            for (int kx = 0; kx < 3; kx++) {
                int xx = x + kx - 1;
                if ((unsigned)xx >= (unsigned)WW) continue;
                int t = ky * 3 + kx;
                s0 += apA[yy*WW + xx] * Va[t * C_IN + ci];
                s1 += apB[yy*WW + xx] * Va[t * C_IN + ci + 1];
            }
        }
    }
    e[i] = s0 + s1;
}

// ---------------- softmax over H*W per batch --------------------------------
__global__ void softmax_k(const float* __restrict__ e, float* __restrict__ a)
{
    __shared__ float red[256];
    const int b = blockIdx.x;
    const float* eb = e + b * HW_;
    float m = -1e30f;
    for (int i = threadIdx.x; i < HW_; i += 256) m = fmaxf(m, eb[i]);
    red[threadIdx.x] = m; __syncthreads();
    for (int s = 128; s > 0; s >>= 1) {
        if (threadIdx.x < s) red[threadIdx.x] = fmaxf(red[threadIdx.x], red[threadIdx.x + s]);
        __syncthreads();
    }
    m = red[0]; __syncthreads();
    float sum = 0.f;
    for (int i = threadIdx.x; i < HW_; i += 256) sum += expf(eb[i] - m);
    red[threadIdx.x] = sum; __syncthreads();
    for (int s = 128; s > 0; s >>= 1) {
        if (threadIdx.x < s) red[threadIdx.x] += red[threadIdx.x + s];
        __syncthreads();
    }
    float inv = 1.f / red[0];
    for (int i = threadIdx.x; i < HW_; i += 256)
        a[b * HW_ + i] = expf(eb[i] - m) * inv;
}

// ---------------- x_tilde = x_t * a (broadcast over channels) ---------------
__global__ void xtilde_k(const float* __restrict__ x_t,  // points at x + t*CHW
                         const float* __restrict__ a,
                         float* __restrict__ xt)
{
    int i = blockIdx.x * blockDim.x + threadIdx.x;
    if (i >= BB*CHW) return;
    int b = i / CHW, r = i % CHW, p = r % HW_;
    xt[i] = x_t[(long)b * (TT*CHW) + r] * a[b * HW_ + p];
}

// ---------------- LSTM pointwise update -------------------------------------
__global__ void lstm_k(const float* __restrict__ g,
                       float* __restrict__ c,
                       float* __restrict__ h,
                       float* __restrict__ out)   // nullptr except last step
{
    int i = blockIdx.x * blockDim.x + threadIdx.x;
    if (i >= BB*CHW) return;
    int b = i / CHW, r = i % CHW;
    const float* gb = g + (long)b * 4 * CHW;
    float gi = gb[r];
    float gf = gb[CHW + r];
    float gc = gb[2*CHW + r];
    float go = gb[3*CHW + r];
    float iv = 1.f / (1.f + expf(-gi));
    float fv = 1.f / (1.f + expf(-gf));
    float ov = 1.f / (1.f + expf(-go));
    float cn = fv * c[i] + iv * tanhf(gc);
    float hn = ov * tanhf(cn);
    c[i] = cn;
    h[i] = hn;
    if (out) out[i] = hn;
}

// ---------------------------------------------------------------------------
extern "C" void kernel_launch(void* const* d_in, const int* in_sizes, int n_in,
                              void* d_out, int out_size)
{
    const float* x   = (const float*)d_in[0];
    const float* Wa  = (const float*)d_in[1];
    const float* ba  = (const float*)d_in[2];
    const float* Ua  = (const float*)d_in[3];
    const float* bua = (const float*)d_in[4];
    const float* Va  = (const float*)d_in[5];
    const float* Wx  = (const float*)d_in[6];
    const float* bx  = (const float*)d_in[7];
    const float* Uh  = (const float*)d_in[8];
    const float* bh  = (const float*)d_in[9];
    float* out = (float*)d_out;

    float *h, *c, *att, *e, *a, *xt, *g;
    cudaGetSymbolAddress((void**)&h,   g_h);
    cudaGetSymbolAddress((void**)&c,   g_c);
    cudaGetSymbolAddress((void**)&att, g_att);
    cudaGetSymbolAddress((void**)&e,   g_e);
    cudaGetSymbolAddress((void**)&a,   g_a);
    cudaGetSymbolAddress((void**)&xt,  g_xt);
    cudaGetSymbolAddress((void**)&g,   g_g);

    const int N  = BB * CHW;           // 1,228,800
    const int NB = (N + 255) / 256;

    init_hc_k<<<NB, 256>>>(x);

    for (int t = 0; t < TT; t++) {
        const float* x_t = x + (long)t * CHW;   // batch stride TT*CHW

        // att = tanh(conv(h,Wa)+ba + conv(x_t,Ua)+bua)
        conv_dual_k<256, true><<<dim3(15, 256/64, BB), 256>>>(
            h, (long)CHW, Wa, x_t, (long)TT*CHW, Ua, ba, bua, att);

        // e = conv(att, Va); a = softmax(e)
        econv_k<<<(BB*HW_ + 255)/256, 256>>>(att, Va, e);
        softmax_k<<<BB, 256>>>(e, a);

        // x_tilde = x_t * a
        xtilde_k<<<NB, 256>>>(x_t, a, xt);

        // g = conv(x_tilde,Wx)+bx + conv(h,Uh)+bh   (4C output channels)
        conv_dual_k<1024, false><<<dim3(15, 1024/64, BB), 256>>>(
            xt, (long)CHW, Wx, h, (long)CHW, Uh, bx, bh, g);

        // gate update; last step also writes d_out
        lstm_k<<<NB, 256>>>(g, c, h, (t == TT-1) ? out : (float*)nullptr);
    }
}

// round 3
// speedup vs baseline: 4.0769x; 4.0769x over previous
#include <cuda_runtime.h>
#include <cuda_bf16.h>
#include <cstdint>
#include <math.h>

#define C_    256
#define HH    30
#define WW    40
#define BB    4
#define TT    4
#define HW_   1200
#define PW    42
#define NP    1344          // 32*42 padded pixels
#define ROWS  1536          // 64 guard + 1344 + 128 guard
#define RBASE 64
#define AROWS 214           // 128 + 2*43
#define SAS   40            // smem k stride in bf16 (32 + 8 pad)

// ---------------- scratch (device globals) ----------------------------------
__device__ __nv_bfloat16 g_Xh [TT*BB*ROWS*C_], g_Xl [TT*BB*ROWS*C_];
__device__ __nv_bfloat16 g_Hh [BB*ROWS*C_],    g_Hl [BB*ROWS*C_];
__device__ __nv_bfloat16 g_XTh[BB*ROWS*C_],    g_XTl[BB*ROWS*C_];
__device__ __nv_bfloat16 g_WAh[2*9*256*C_],    g_WAl[2*9*256*C_];
__device__ __nv_bfloat16 g_WGh[2*9*1024*C_],   g_WGl[2*9*1024*C_];
__device__ float g_att[BB*NP*C_];
__device__ float g_gt [BB*(long)NP*1024];
__device__ float g_cS [BB*NP*C_];
__device__ float g_e  [BB*HW_];
__device__ float g_a  [BB*HW_];

// ---------------- PTX helpers ------------------------------------------------
#define LDSM4(arr, addr) asm volatile( \
    "ldmatrix.sync.aligned.m8n8.x4.shared.b16 {%0,%1,%2,%3}, [%4];" \
    : "=r"((arr)[0]), "=r"((arr)[1]), "=r"((arr)[2]), "=r"((arr)[3]) : "r"(addr))
#define LDSM2(arr, addr) asm volatile( \
    "ldmatrix.sync.aligned.m8n8.x2.shared.b16 {%0,%1}, [%2];" \
    : "=r"((arr)[0]), "=r"((arr)[1]) : "r"(addr))
#define MMA_BF16(d, a, bfr) asm volatile( \
    "mma.sync.aligned.m16n8k16.row.col.f32.bf16.bf16.f32 " \
    "{%0,%1,%2,%3}, {%4,%5,%6,%7}, {%8,%9}, {%0,%1,%2,%3};" \
    : "+f"((d)[0]), "+f"((d)[1]), "+f"((d)[2]), "+f"((d)[3]) \
    : "r"((a)[0]), "r"((a)[1]), "r"((a)[2]), "r"((a)[3]), "r"((bfr)[0]), "r"((bfr)[1]))

__device__ __forceinline__ uint32_t s2u(const void* p) {
    return (uint32_t)__cvta_generic_to_shared(p);
}
__device__ __forceinline__ void splitf(float v, __nv_bfloat16& h, __nv_bfloat16& l) {
    h = __float2bfloat16_rn(v);
    l = __float2bfloat16_rn(v - __bfloat162float(h));
}

// ---------------- activation transpose + split: x NCHW -> [t][b][rows][ci] --
__global__ void xprep_k(const float* __restrict__ x) {
    __shared__ float tile[32][33];
    const int tx = threadIdx.x, ty = threadIdx.y;
    const int p0 = blockIdx.x * 32, ci0 = blockIdx.y * 32;
    const int t = blockIdx.z >> 2, b = blockIdx.z & 3;
    const float* src = x + (((long)b*TT + t)*C_ + ci0) * HW_;
    for (int i = ty; i < 32; i += 8) {
        int p = p0 + tx;
        tile[i][tx] = (p < HW_) ? src[(long)i*HW_ + p] : 0.f;
    }
    __syncthreads();
    __nv_bfloat16* dh = g_Xh + ((long)t*BB + b) * ROWS * C_;
    __nv_bfloat16* dl = g_Xl + ((long)t*BB + b) * ROWS * C_;
    for (int i = ty; i < 32; i += 8) {
        int p = p0 + i;
        if (p >= HW_) continue;
        int q = (p/WW + 1)*PW + (p%WW) + 1;
        float v = tile[tx][i];
        __nv_bfloat16 h, l; splitf(v, h, l);
        long o = ((long)(RBASE + q))*C_ + ci0 + tx;
        dh[o] = h; dl[o] = l;
    }
}

// ---------------- weight transpose + split: HWIO -> [j][t][co][ci] ----------
__global__ void wprep_k(const float* __restrict__ W, __nv_bfloat16* __restrict__ Dh,
                        __nv_bfloat16* __restrict__ Dl, int cout, int jslot) {
    __shared__ float tile[32][33];
    const int tx = threadIdx.x, ty = threadIdx.y;
    const int t = blockIdx.x, co0 = blockIdx.y * 32, ci0 = blockIdx.z * 32;
    for (int i = ty; i < 32; i += 8)
        tile[i][tx] = W[((long)t*C_ + ci0 + i)*cout + co0 + tx];   // tile[ci][co]
    __syncthreads();
    for (int i = ty; i < 32; i += 8) {
        float v = tile[tx][i];                                     // (ci0+tx, co0+i)
        __nv_bfloat16 h, l; splitf(v, h, l);
        long o = (((long)jslot*9 + t)*cout + co0 + i)*C_ + ci0 + tx;
        Dh[o] = h; Dl[o] = l;
    }
}

// ---------------- h0 = c0 = sum_t x -----------------------------------------
__global__ void init_hc_k() {
    int i = blockIdx.x * blockDim.x + threadIdx.x;
    if (i >= BB*HW_*C_) return;
    int ci = i & 255, rest = i >> 8;
    int p = rest % HW_, b = rest / HW_;
    int q = (p/WW + 1)*PW + (p%WW) + 1;
    float s = 0.f;
#pragma unroll
    for (int t = 0; t < TT; t++) {
        long ix = (((long)t*BB + b)*ROWS + RBASE + q)*C_ + ci;
        s += __bfloat162float(g_Xh[ix]) + __bfloat162float(g_Xl[ix]);
    }
    g_cS[((long)b*NP + q)*C_ + ci] = s;
    __nv_bfloat16 h, l; splitf(s, h, l);
    long ho = ((long)b*ROWS + RBASE + q)*C_ + ci;
    g_Hh[ho] = h; g_Hl[ho] = l;
}

// ---------------- dual-input 3x3 conv as 9-tap shifted GEMM (bf16x3 MMA) ----
// D[q, co] = sum_{j,t,ci} A_j[q+delta_t, ci] * W_j[t, ci, co]   (+bias, opt tanh)
template<int COUT, bool DO_TANH>
__global__ __launch_bounds__(256)
void conv_mma_k(const __nv_bfloat16* __restrict__ A1h, const __nv_bfloat16* __restrict__ A1l,
                const __nv_bfloat16* __restrict__ A2h, const __nv_bfloat16* __restrict__ A2l,
                const __nv_bfloat16* __restrict__ Wh,  const __nv_bfloat16* __restrict__ Wl,
                const float* __restrict__ bias1, const float* __restrict__ bias2,
                float* __restrict__ outp)
{
    __shared__ __align__(16) __nv_bfloat16 sA[2][AROWS*SAS];   // hi/lo, 214 rows x 32k
    __shared__ __align__(16) __nv_bfloat16 sB[2][64*SAS];      // hi/lo, 64 co x 32k

    const int tid = threadIdx.x, lane = tid & 31, wid = tid >> 5;
    const int q0  = blockIdx.x * 128;
    const int co0 = blockIdx.y * 64;
    const int b   = blockIdx.z;
    const int wm  = (wid & 1) * 64;        // warp m offset in tile
    const int wn  = (wid >> 1) * 16;       // warp n offset in tile

    float acc[4][2][4];
#pragma unroll
    for (int mt = 0; mt < 4; mt++)
#pragma unroll
        for (int nt = 0; nt < 2; nt++)
#pragma unroll
            for (int k = 0; k < 4; k++) acc[mt][nt][k] = 0.f;

    const int lr = lane & 7, ls = lane >> 3;
    const int arow = ((ls & 1) << 3) + lr;     // ldmatrix A row-within-16
    const int acol = (ls >> 1) << 3;           // ldmatrix A col sel (0/8)
    const int bcol = (ls & 1) << 3;            // ldmatrix B col sel (0/8)

    const long boff = (long)b * (ROWS * C_);

#pragma unroll 1
    for (int j = 0; j < 2; j++) {
        const __nv_bfloat16* Ah = (j ? A2h : A1h) + boff + (long)(RBASE + q0 - 43) * C_;
        const __nv_bfloat16* Al = (j ? A2l : A1l) + boff + (long)(RBASE + q0 - 43) * C_;
        const __nv_bfloat16* Wjh = Wh + (long)j * 9 * COUT * C_;
        const __nv_bfloat16* Wjl = Wl + (long)j * 9 * COUT * C_;
#pragma unroll 1
        for (int kc = 0; kc < 8; kc++) {
            __syncthreads();
            // stage A tile (214 rows x 32 k) hi+lo
            for (int idx = tid; idx < AROWS*8; idx += 256) {
                int r = idx >> 3, s = idx & 7;
                long go = (long)r * C_ + kc*32 + s*4;
                *(uint2*)&sA[0][r*SAS + s*4] = *(const uint2*)(Ah + go);
                *(uint2*)&sA[1][r*SAS + s*4] = *(const uint2*)(Al + go);
            }
#pragma unroll 1
            for (int t = 0; t < 9; t++) {
                __syncthreads();   // prev tap's MMAs done (and A visible on t=0)
                {
                    int idx = tid;
#pragma unroll
                    for (int it = 0; it < 2; it++, idx += 256) {
                        int r = idx >> 3, s = idx & 7;
                        long wo = ((long)t*COUT + co0 + r)*C_ + kc*32 + s*4;
                        *(uint2*)&sB[0][r*SAS + s*4] = *(const uint2*)(Wjh + wo);
                        *(uint2*)&sB[1][r*SAS + s*4] = *(const uint2*)(Wjl + wo);
                    }
                }
                __syncthreads();
                const int dy = t/3 - 1, dx = t%3 - 1;
                const int aoff = (dy*PW + dx + 43) * SAS;
#pragma unroll
                for (int kk = 0; kk < 2; kk++) {
                    const int kcol = kk * 16;
                    uint32_t afh[4][4], afl[4][4];
#pragma unroll
                    for (int mt = 0; mt < 4; mt++) {
                        int rr = aoff + (wm + mt*16 + arow)*SAS + kcol + acol;
                        LDSM4(afh[mt], s2u(&sA[0][rr]));
                        LDSM4(afl[mt], s2u(&sA[1][rr]));
                    }
                    uint32_t bfh[2][2], bfl[2][2];
#pragma unroll
                    for (int nt = 0; nt < 2; nt++) {
                        int rr = (wn + nt*8 + lr)*SAS + kcol + bcol;
                        LDSM2(bfh[nt], s2u(&sB[0][rr]));
                        LDSM2(bfl[nt], s2u(&sB[1][rr]));
                    }
#pragma unroll
                    for (int mt = 0; mt < 4; mt++)
#pragma unroll
                        for (int nt = 0; nt < 2; nt++) {
                            MMA_BF16(acc[mt][nt], afh[mt], bfh[nt]);
                            MMA_BF16(acc[mt][nt], afh[mt], bfl[nt]);
                            MMA_BF16(acc[mt][nt], afl[mt], bfh[nt]);
                        }
                }
            }
        }
    }

    // epilogue
    const int g = lane >> 2, tg = lane & 3;
#pragma unroll
    for (int nt = 0; nt < 2; nt++) {
        int col = co0 + wn + nt*8 + tg*2;
        float b0v = bias1[col]   + bias2[col];
        float b1v = bias1[col+1] + bias2[col+1];
#pragma unroll
        for (int mt = 0; mt < 4; mt++) {
            int r0 = q0 + wm + mt*16 + g;
            float v0 = acc[mt][nt][0] + b0v, v1 = acc[mt][nt][1] + b1v;
            float v2 = acc[mt][nt][2] + b0v, v3 = acc[mt][nt][3] + b1v;
            if (DO_TANH) { v0 = tanhf(v0); v1 = tanhf(v1); v2 = tanhf(v2); v3 = tanhf(v3); }
            if (r0 < NP) {
                float2 w = make_float2(v0, v1);
                *(float2*)&outp[((long)b*NP + r0)*COUT + col] = w;
            }
            if (r0 + 8 < NP) {
                float2 w = make_float2(v2, v3);
                *(float2*)&outp[((long)b*NP + r0 + 8)*COUT + col] = w;
            }
        }
    }
}

// ---------------- e = conv3x3(att, Va), 256 -> 1 ----------------------------
__global__ void econv_k(const float* __restrict__ Va) {
    __shared__ float red[256];
    const int p = blockIdx.x, b = blockIdx.y;
    const int y = p / WW, x = p % WW;
    const int q = (y+1)*PW + (x+1);
    const int ci = threadIdx.x;
    const float* ab = g_att + (long)b*NP*C_;
    float s = 0.f;
#pragma unroll
    for (int t = 0; t < 9; t++) {
        int yy = y + t/3 - 1, xx = x + t%3 - 1;
        if ((unsigned)yy < (unsigned)HH && (unsigned)xx < (unsigned)WW) {
            int dq = q + (t/3 - 1)*PW + (t%3 - 1);
            s += ab[(long)dq*C_ + ci] * Va[t*C_ + ci];
        }
    }
    red[ci] = s; __syncthreads();
    for (int st = 128; st > 0; st >>= 1) {
        if (ci < st) red[ci] += red[ci + st];
        __syncthreads();
    }
    if (ci == 0) g_e[b*HW_ + p] = red[0];
}

// ---------------- softmax over H*W per batch --------------------------------
__global__ void softmax_k() {
    __shared__ float red[256];
    const int b = blockIdx.x;
    const float* eb = g_e + b*HW_;
    float m = -1e30f;
    for (int i = threadIdx.x; i < HW_; i += 256) m = fmaxf(m, eb[i]);
    red[threadIdx.x] = m; __syncthreads();
    for (int s = 128; s > 0; s >>= 1) {
        if (threadIdx.x < s) red[threadIdx.x] = fmaxf(red[threadIdx.x], red[threadIdx.x+s]);
        __syncthreads();
    }
    m = red[0]; __syncthreads();
    float sum = 0.f;
    for (int i = threadIdx.x; i < HW_; i += 256) sum += expf(eb[i] - m);
    red[threadIdx.x] = sum; __syncthreads();
    for (int s = 128; s > 0; s >>= 1) {
        if (threadIdx.x < s) red[threadIdx.x] += red[threadIdx.x+s];
        __syncthreads();
    }
    float inv = 1.f / red[0];
    for (int i = threadIdx.x; i < HW_; i += 256)
        g_a[b*HW_ + i] = expf(eb[i] - m) * inv;
}

// ---------------- x_tilde = x_t * a, split to bf16 hi/lo --------------------
__global__ void xtilde_k(const __nv_bfloat16* __restrict__ Xth,
                         const __nv_bfloat16* __restrict__ Xtl) {
    int i = blockIdx.x * blockDim.x + threadIdx.x;
    if (i >= BB*HW_*C_) return;
    int ci = i & 255, rest = i >> 8;
    int p = rest % HW_, b = rest / HW_;
    int q = (p/WW + 1)*PW + (p%WW) + 1;
    long ix = ((long)b*ROWS + RBASE + q)*C_ + ci;
    float v = __bfloat162float(Xth[ix]) + __bfloat162float(Xtl[ix]);
    v *= g_a[b*HW_ + p];
    __nv_bfloat16 h, l; splitf(v, h, l);
    g_XTh[ix] = h; g_XTl[ix] = l;
}

// ---------------- LSTM pointwise update -------------------------------------
__global__ void lstm_k(float* __restrict__ outp) {   // outp nullptr except last step
    int i = blockIdx.x * blockDim.x + threadIdx.x;
    if (i >= BB*HW_*C_) return;
    int ci = i & 255, rest = i >> 8;
    int p = rest % HW_, b = rest / HW_;
    int q = (p/WW + 1)*PW + (p%WW) + 1;
    long gb = ((long)b*NP + q)*1024 + ci;
    float gi = g_gt[gb], gf = g_gt[gb+256], gcv = g_gt[gb+512], go = g_gt[gb+768];
    long cix = ((long)b*NP + q)*C_ + ci;
    float iv = 1.f / (1.f + expf(-gi));
    float fv = 1.f / (1.f + expf(-gf));
    float ov = 1.f / (1.f + expf(-go));
    float cn = fv * g_cS[cix] + iv * tanhf(gcv);
    float hn = ov * tanhf(cn);
    g_cS[cix] = cn;
    __nv_bfloat16 h, l; splitf(hn, h, l);
    long ho = ((long)b*ROWS + RBASE + q)*C_ + ci;
    g_Hh[ho] = h; g_Hl[ho] = l;
    if (outp) outp[((long)b*C_ + ci)*HW_ + p] = hn;
}

// ---------------------------------------------------------------------------
extern "C" void kernel_launch(void* const* d_in, const int* in_sizes, int n_in,
                              void* d_out, int out_size)
{
    const float* x   = (const float*)d_in[0];
    const float* Wa  = (const float*)d_in[1];
    const float* ba  = (const float*)d_in[2];
    const float* Ua  = (const float*)d_in[3];
    const float* bua = (const float*)d_in[4];
    const float* Va  = (const float*)d_in[5];
    const float* Wx  = (const float*)d_in[6];
    const float* bx  = (const float*)d_in[7];
    const float* Uh  = (const float*)d_in[8];
    const float* bh  = (const float*)d_in[9];
    float* out = (float*)d_out;

    void *pXh, *pXl, *pHh, *pHl, *pXTh, *pXTl, *pWAh, *pWAl, *pWGh, *pWGl, *pAtt, *pG;
    cudaGetSymbolAddress(&pXh,  g_Xh);  cudaGetSymbolAddress(&pXl,  g_Xl);
    cudaGetSymbolAddress(&pHh,  g_Hh);  cudaGetSymbolAddress(&pHl,  g_Hl);
    cudaGetSymbolAddress(&pXTh, g_XTh); cudaGetSymbolAddress(&pXTl, g_XTl);
    cudaGetSymbolAddress(&pWAh, g_WAh); cudaGetSymbolAddress(&pWAl, g_WAl);
    cudaGetSymbolAddress(&pWGh, g_WGh); cudaGetSymbolAddress(&pWGl, g_WGl);
    cudaGetSymbolAddress(&pAtt, g_att); cudaGetSymbolAddress(&pG,   g_gt);

    // zero guard borders (interiors rewritten every call)
    cudaMemsetAsync(pXh,  0, sizeof(__nv_bfloat16)*TT*BB*ROWS*C_);
    cudaMemsetAsync(pXl,  0, sizeof(__nv_bfloat16)*TT*BB*ROWS*C_);
    cudaMemsetAsync(pHh,  0, sizeof(__nv_bfloat16)*BB*ROWS*C_);
    cudaMemsetAsync(pHl,  0, sizeof(__nv_bfloat16)*BB*ROWS*C_);
    cudaMemsetAsync(pXTh, 0, sizeof(__nv_bfloat16)*BB*ROWS*C_);
    cudaMemsetAsync(pXTl, 0, sizeof(__nv_bfloat16)*BB*ROWS*C_);

    // prep: transpose+split activations and weights
    xprep_k<<<dim3(38, 8, 16), dim3(32, 8)>>>(x);
    wprep_k<<<dim3(9,  8, 8), dim3(32, 8)>>>(Wa, (__nv_bfloat16*)pWAh, (__nv_bfloat16*)pWAl, 256,  0);
    wprep_k<<<dim3(9,  8, 8), dim3(32, 8)>>>(Ua, (__nv_bfloat16*)pWAh, (__nv_bfloat16*)pWAl, 256,  1);
    wprep_k<<<dim3(9, 32, 8), dim3(32, 8)>>>(Wx, (__nv_bfloat16*)pWGh, (__nv_bfloat16*)pWGl, 1024, 0);
    wprep_k<<<dim3(9, 32, 8), dim3(32, 8)>>>(Uh, (__nv_bfloat16*)pWGh, (__nv_bfloat16*)pWGl, 1024, 1);

    const int NPT = BB*HW_*C_;            // 1,228,800
    const int NB  = (NPT + 255) / 256;    // 4800
    init_hc_k<<<NB, 256>>>();

    const __nv_bfloat16* Xh = (const __nv_bfloat16*)pXh;
    const __nv_bfloat16* Xl = (const __nv_bfloat16*)pXl;
    const long tstride = (long)BB * ROWS * C_;

    for (int t = 0; t < TT; t++) {
        // att = tanh(conv(h,Wa)+ba + conv(x_t,Ua)+bua)
        conv_mma_k<256, true><<<dim3(11, 4, BB), 256>>>(
            (const __nv_bfloat16*)pHh, (const __nv_bfloat16*)pHl,
            Xh + t*tstride, Xl + t*tstride,
            (const __nv_bfloat16*)pWAh, (const __nv_bfloat16*)pWAl,
            ba, bua, (float*)pAtt);

        econv_k<<<dim3(HW_, BB), 256>>>(Va);
        softmax_k<<<BB, 256>>>();
        xtilde_k<<<NB, 256>>>(Xh + t*tstride, Xl + t*tstride);

        // g = conv(x_tilde,Wx)+bx + conv(h,Uh)+bh
        conv_mma_k<1024, false><<<dim3(11, 16, BB), 256>>>(
            (const __nv_bfloat16*)pXTh, (const __nv_bfloat16*)pXTl,
            (const __nv_bfloat16*)pHh, (const __nv_bfloat16*)pHl,
            (const __nv_bfloat16*)pWGh, (const __nv_bfloat16*)pWGl,
            bx, bh, (float*)pG);

        lstm_k<<<NB, 256>>>((t == TT-1) ? out : (float*)nullptr);
    }
}